// round 1
// baseline (speedup 1.0000x reference)
#include <cuda_runtime.h>

// Problem constants
#define BB      32
#define NN      8192
#define HH      512
#define K2      256      // H/2
#define TM      64       // points per CTA
#define THREADS 256
#define LN_EPS  1e-5f
#define SLOPE   0.2f
#define KT      16       // W2 k-chunk staged in smem

// Shared memory layout (floats):
//   h1   [TM][HH]        = 32768
//   w2s  [2][KT][K2]     =  8192
//   w1s  [3][HH]         =  1536
//   b1s/g1s/be1s [HH]x3  =  1536
//   b2s/g2s/be2s [K2]x3  =   768
//   w3s  [K2][3]         =   768
//   b3s  [4]             =     4
// total 45572 floats = 182288 bytes
#define SMEM_FLOATS 45572

__device__ __forceinline__ float warp_sum(float v) {
#pragma unroll
    for (int o = 16; o; o >>= 1) v += __shfl_xor_sync(0xffffffffu, v, o);
    return v;
}

extern __shared__ float smem[];

__global__ __launch_bounds__(THREADS, 1)
void shape_prior_fused(const float* __restrict__ points,
                       const int*   __restrict__ cat,
                       const float* __restrict__ W1, const float* __restrict__ b1,
                       const float* __restrict__ g1, const float* __restrict__ be1,
                       const float* __restrict__ W2, const float* __restrict__ b2,
                       const float* __restrict__ g2, const float* __restrict__ be2,
                       const float* __restrict__ W3, const float* __restrict__ b3,
                       float* __restrict__ out)
{
    float* h1   = smem;                  // [TM][HH]
    float* w2s  = h1   + TM * HH;        // [2][KT][K2]
    float* w1s  = w2s  + 2 * KT * K2;    // [3][HH]
    float* b1s  = w1s  + 3 * HH;
    float* g1s  = b1s  + HH;
    float* be1s = g1s  + HH;
    float* b2s  = be1s + HH;
    float* g2s  = b2s  + K2;
    float* be2s = g2s  + K2;
    float* w3s  = be2s + K2;             // [K2][3]
    float* b3s  = w3s  + K2 * 3;         // [4]

    const int tid  = threadIdx.x;
    const int b    = blockIdx.y;
    const int m0   = blockIdx.x * TM;
    const int ci   = cat[b];

    // ---- Stage small per-expert params ----
    {
        const float* W1g = W1 + ci * 3 * HH;
        for (int i = tid; i < 3 * HH; i += THREADS) w1s[i] = W1g[i];
        for (int i = tid; i < HH; i += THREADS) {
            b1s[i]  = b1 [ci * HH + i];
            g1s[i]  = g1 [ci * HH + i];
            be1s[i] = be1[ci * HH + i];
        }
        for (int i = tid; i < K2; i += THREADS) {
            b2s[i]  = b2 [ci * K2 + i];
            g2s[i]  = g2 [ci * K2 + i];
            be2s[i] = be2[ci * K2 + i];
        }
        for (int i = tid; i < K2 * 3; i += THREADS) w3s[i] = W3[ci * K2 * 3 + i];
        if (tid < 3) b3s[tid] = b3[ci * 3 + tid];
    }
    __syncthreads();

    const int wid  = tid >> 5;   // warp id 0..7 (also ty for GEMM2)
    const int lane = tid & 31;   // also tx for GEMM2

    // ---- Phase 1: GEMM1 (K=3) + LayerNorm1 + LeakyReLU -> h1 in smem ----
    // Warp `wid` owns rows wid*8 .. wid*8+7. Each lane covers cols lane+32*i.
#pragma unroll 1
    for (int r = 0; r < 8; r++) {
        const int m = wid * 8 + r;
        const float* pp = points + (b * NN + m0 + m) * 3;
        const float p0 = pp[0], p1 = pp[1], p2 = pp[2];

        float x[16];
        float s = 0.f;
#pragma unroll
        for (int i = 0; i < 16; i++) {
            const int j = lane + 32 * i;
            x[i] = fmaf(p0, w1s[j],
                   fmaf(p1, w1s[HH + j],
                   fmaf(p2, w1s[2 * HH + j], b1s[j])));
            s += x[i];
        }
        s = warp_sum(s);
        const float mu = s * (1.f / HH);
        float sq = 0.f;
#pragma unroll
        for (int i = 0; i < 16; i++) { const float d = x[i] - mu; sq = fmaf(d, d, sq); }
        sq = warp_sum(sq);
        const float inv = rsqrtf(sq * (1.f / HH) + LN_EPS);
#pragma unroll
        for (int i = 0; i < 16; i++) {
            const int j = lane + 32 * i;
            float y = (x[i] - mu) * inv * g1s[j] + be1s[j];
            y = (y >= 0.f) ? y : SLOPE * y;
            h1[m * HH + j] = y;   // lanes write consecutive words: conflict-free
        }
    }
    // h1 completeness is guaranteed by the __syncthreads at top of first chunk below.

    // ---- Phase 2: GEMM2  C[64,256] = h1[64,512] @ W2[512,256] ----
    // Thread (ty=wid, tx=lane) owns rows ty*8+r (r<8), cols tx+32*c (c<8).
    float acc[8][8];
#pragma unroll
    for (int r = 0; r < 8; r++)
#pragma unroll
        for (int c = 0; c < 8; c++) acc[r][c] = 0.f;

    const float* W2g = W2 + ci * HH * K2;

    float4 rr[4];
    {   // preload chunk 0 into registers, then smem buf 0
        const float4* src = (const float4*)W2g;
#pragma unroll
        for (int i = 0; i < 4; i++) rr[i] = src[tid + 256 * i];
        float4* dst = (float4*)w2s;
#pragma unroll
        for (int i = 0; i < 4; i++) dst[tid + 256 * i] = rr[i];
    }

    int buf = 0;
#pragma unroll 1
    for (int kc = 0; kc < HH / KT; kc++) {
        __syncthreads();   // buf ready for everyone; prev compute finished

        if (kc < HH / KT - 1) {   // prefetch next chunk into registers
            const float4* src = (const float4*)(W2g + (kc + 1) * KT * K2);
#pragma unroll
            for (int i = 0; i < 4; i++) rr[i] = src[tid + 256 * i];
        }

        const float* hp = h1  + (wid * 8) * HH + kc * KT;
        const float* bp = w2s + buf * (KT * K2) + lane;
#pragma unroll
        for (int kk = 0; kk < KT; kk++) {
            float a[8], bv[8];
#pragma unroll
            for (int r = 0; r < 8; r++) a[r] = hp[r * HH + kk];        // broadcast
#pragma unroll
            for (int c = 0; c < 8; c++) bv[c] = bp[kk * K2 + 32 * c];  // conflict-free
#pragma unroll
            for (int r = 0; r < 8; r++)
#pragma unroll
                for (int c = 0; c < 8; c++)
                    acc[r][c] = fmaf(a[r], bv[c], acc[r][c]);
        }

        if (kc < HH / KT - 1) {   // commit prefetched chunk to the other buffer
            buf ^= 1;
            float4* dst = (float4*)(w2s + buf * (KT * K2));
#pragma unroll
            for (int i = 0; i < 4; i++) dst[tid + 256 * i] = rr[i];
        }
    }

    // ---- Phase 3: bias2 + LayerNorm2 + LeakyReLU + GEMM3 (N=3) -> out ----
#pragma unroll 1
    for (int r = 0; r < 8; r++) {
        const int m = wid * 8 + r;
        float s = 0.f;
#pragma unroll
        for (int c = 0; c < 8; c++) {
            acc[r][c] += b2s[lane + 32 * c];
            s += acc[r][c];
        }
        s = warp_sum(s);
        const float mu = s * (1.f / K2);
        float sq = 0.f;
#pragma unroll
        for (int c = 0; c < 8; c++) { const float d = acc[r][c] - mu; sq = fmaf(d, d, sq); }
        sq = warp_sum(sq);
        const float inv = rsqrtf(sq * (1.f / K2) + LN_EPS);

        float o0 = 0.f, o1 = 0.f, o2 = 0.f;
#pragma unroll
        for (int c = 0; c < 8; c++) {
            const int n = lane + 32 * c;
            float y = (acc[r][c] - mu) * inv * g2s[n] + be2s[n];
            y = (y >= 0.f) ? y : SLOPE * y;
            o0 = fmaf(y, w3s[n * 3 + 0], o0);
            o1 = fmaf(y, w3s[n * 3 + 1], o1);
            o2 = fmaf(y, w3s[n * 3 + 2], o2);
        }
        o0 = warp_sum(o0); o1 = warp_sum(o1); o2 = warp_sum(o2);
        if (lane == 0) {
            float* op = out + (b * NN + m0 + m) * 3;
            op[0] = o0 + b3s[0];
            op[1] = o1 + b3s[1];
            op[2] = o2 + b3s[2];
        }
    }
}

extern "C" void kernel_launch(void* const* d_in, const int* in_sizes, int n_in,
                              void* d_out, int out_size)
{
    const float* points = (const float*)d_in[0];
    const int*   cat    = (const int*)  d_in[1];
    const float* W1     = (const float*)d_in[2];
    const float* b1     = (const float*)d_in[3];
    const float* g1     = (const float*)d_in[4];
    const float* be1    = (const float*)d_in[5];
    const float* W2     = (const float*)d_in[6];
    const float* b2     = (const float*)d_in[7];
    const float* g2     = (const float*)d_in[8];
    const float* be2    = (const float*)d_in[9];
    const float* W3     = (const float*)d_in[10];
    const float* b3     = (const float*)d_in[11];
    float* out = (float*)d_out;

    const size_t smem_bytes = (size_t)SMEM_FLOATS * sizeof(float);
    cudaFuncSetAttribute(shape_prior_fused,
                         cudaFuncAttributeMaxDynamicSharedMemorySize,
                         (int)smem_bytes);

    dim3 grid(NN / TM, BB);
    shape_prior_fused<<<grid, THREADS, smem_bytes>>>(
        points, cat, W1, b1, g1, be1, W2, b2, g2, be2, W3, b3, out);
}

// round 3
// speedup vs baseline: 3.0508x; 3.0508x over previous
#include <cuda_runtime.h>
#include <cstdint>

#define BB      32
#define NN      8192
#define HH      512
#define K2      256
#define TM      128
#define THREADS 256
#define EPSLN   1e-5f
#define SLOPE   0.2f
#define KC      32
#define NCH     (HH / KC)       // 16 k-chunks
#define NE      10

// Transposed + tf32-rounded W2 scratch: W2T[e][n][k] = tf32(W2[e][k][n])
__device__ float g_W2T[NE * K2 * HH];

// ---------------- smem layout (bytes) ----------------
// Region [0, 132096): mainloop A/B double buffers, then epilogue C[128][258]
//   A0 @ 0      (128 rows x 144B = 18432)
//   A1 @ 18432
//   B0 @ 36864  (256 rows x 144B = 36864)
//   B1 @ 73728            (ends 110592)
// Params (floats) @ 132096
#define A0_OFF 0u
#define A1_OFF 18432u
#define B0_OFF 36864u
#define B1_OFF 73728u
#define CSTR   258            // C row stride in floats
#define P_OFF  132096u
// float indices inside params region
#define F_W1    0             // [3][512]
#define F_B1    1536
#define F_G1    2048
#define F_BE1   2560
#define F_B2    3072
#define F_G2    3328
#define F_BE2   3584
#define F_W3    3840          // [256][3]
#define F_B3    4608
#define F_PTS   4612          // [128][3]
#define F_MU    4996
#define F_RS    5124
#define F_END   5252
#define SMEM_TOTAL (P_OFF + F_END * 4)   // 153104 B

__device__ __forceinline__ uint32_t smem_u32(const void* p) {
    uint32_t a;
    asm("{ .reg .u64 t; cvta.to.shared.u64 t, %1; cvt.u32.u64 %0, t; }" : "=r"(a) : "l"(p));
    return a;
}
__device__ __forceinline__ uint32_t f2tf(float x) {
    uint32_t r; asm("cvt.rna.tf32.f32 %0, %1;" : "=r"(r) : "f"(x)); return r;
}
__device__ __forceinline__ float warp_sum(float v) {
#pragma unroll
    for (int o = 16; o; o >>= 1) v += __shfl_xor_sync(0xffffffffu, v, o);
    return v;
}
__device__ __forceinline__ void ldsm4(uint32_t* r, uint32_t addr) {
    asm volatile("ldmatrix.sync.aligned.m8n8.x4.shared.b16 {%0,%1,%2,%3}, [%4];"
                 : "=r"(r[0]), "=r"(r[1]), "=r"(r[2]), "=r"(r[3]) : "r"(addr));
}
__device__ __forceinline__ void mma_tf32(float* c, const uint32_t* a, uint32_t b0, uint32_t b1) {
    asm volatile("mma.sync.aligned.m16n8k8.row.col.f32.tf32.tf32.f32 "
                 "{%0,%1,%2,%3}, {%4,%5,%6,%7}, {%8,%9}, {%0,%1,%2,%3};"
                 : "+f"(c[0]), "+f"(c[1]), "+f"(c[2]), "+f"(c[3])
                 : "r"(a[0]), "r"(a[1]), "r"(a[2]), "r"(a[3]), "r"(b0), "r"(b1));
}
__device__ __forceinline__ void cp16(uint32_t dst, const void* src) {
    asm volatile("cp.async.cg.shared.global [%0], [%1], 16;" :: "r"(dst), "l"(src));
}

// ------------- W2 transpose + tf32 round pre-kernel -------------
__global__ void transpose_w2(const float* __restrict__ W2) {
    __shared__ float t[32][33];
    const int e  = blockIdx.z;
    const int kb = blockIdx.x * 32, nb = blockIdx.y * 32;
    const int tx = threadIdx.x, ty = threadIdx.y;
    const float* src = W2 + e * HH * K2;
    float* dst = g_W2T + e * K2 * HH;
#pragma unroll
    for (int r = 0; r < 32; r += 8)
        t[ty + r][tx] = src[(kb + ty + r) * K2 + nb + tx];
    __syncthreads();
#pragma unroll
    for (int r = 0; r < 32; r += 8)
        dst[(nb + ty + r) * HH + kb + tx] = __uint_as_float(f2tf(t[tx][ty + r]));
}

extern __shared__ char smem_raw[];

__global__ __launch_bounds__(THREADS, 1)
void shape_prior_mma(const float* __restrict__ points, const int* __restrict__ cat,
                     const float* __restrict__ W1, const float* __restrict__ b1,
                     const float* __restrict__ g1, const float* __restrict__ be1,
                     const float* __restrict__ b2, const float* __restrict__ g2,
                     const float* __restrict__ be2,
                     const float* __restrict__ W3, const float* __restrict__ b3,
                     float* __restrict__ out)
{
    float* pf  = (float*)(smem_raw + P_OFF);
    float* csm = (float*)smem_raw;
    const int tid  = threadIdx.x;
    const int wid  = tid >> 5;
    const int lane = tid & 31;
    const int bIdx = blockIdx.y;
    const int m0   = blockIdx.x * TM;
    const int ci   = cat[bIdx];
    const uint32_t sbase = smem_u32(smem_raw);

    // ---- stage per-expert params + points ----
    for (int i = tid; i < 3 * HH; i += THREADS) pf[F_W1 + i] = W1[ci * 3 * HH + i];
    for (int i = tid; i < HH; i += THREADS) {
        pf[F_B1  + i] = b1 [ci * HH + i];
        pf[F_G1  + i] = g1 [ci * HH + i];
        pf[F_BE1 + i] = be1[ci * HH + i];
    }
    for (int i = tid; i < K2; i += THREADS) {
        pf[F_B2  + i] = b2 [ci * K2 + i];
        pf[F_G2  + i] = g2 [ci * K2 + i];
        pf[F_BE2 + i] = be2[ci * K2 + i];
    }
    for (int i = tid; i < K2 * 3; i += THREADS) pf[F_W3 + i] = W3[ci * K2 * 3 + i];
    if (tid < 3) pf[F_B3 + tid] = b3[ci * 3 + tid];
    for (int i = tid; i < TM * 3; i += THREADS)
        pf[F_PTS + i] = points[(size_t)(bIdx * NN + m0) * 3 + i];
    __syncthreads();

    // ---- pass 1: per-point LN1 stats (mu, rstd); h1 not stored ----
#pragma unroll 1
    for (int p = 0; p < 16; p++) {
        const int m = wid * 16 + p;
        const float p0 = pf[F_PTS + m * 3 + 0];
        const float p1 = pf[F_PTS + m * 3 + 1];
        const float p2 = pf[F_PTS + m * 3 + 2];
        float s = 0.f, s2 = 0.f;
#pragma unroll
        for (int q = 0; q < 4; q++) {
            const int k = lane * 16 + q * 4;
            const float4 a0 = *(const float4*)(pf + F_W1 + k);
            const float4 a1 = *(const float4*)(pf + F_W1 + 512 + k);
            const float4 a2 = *(const float4*)(pf + F_W1 + 1024 + k);
            const float4 bb = *(const float4*)(pf + F_B1 + k);
            const float h0 = fmaf(p0, a0.x, fmaf(p1, a1.x, fmaf(p2, a2.x, bb.x)));
            const float h1v= fmaf(p0, a0.y, fmaf(p1, a1.y, fmaf(p2, a2.y, bb.y)));
            const float h2 = fmaf(p0, a0.z, fmaf(p1, a1.z, fmaf(p2, a2.z, bb.z)));
            const float h3 = fmaf(p0, a0.w, fmaf(p1, a1.w, fmaf(p2, a2.w, bb.w)));
            s += h0 + h1v + h2 + h3;
            s2 = fmaf(h0, h0, s2); s2 = fmaf(h1v, h1v, s2);
            s2 = fmaf(h2, h2, s2); s2 = fmaf(h3, h3, s2);
        }
        s  = warp_sum(s);
        s2 = warp_sum(s2);
        if (lane == 0) {
            const float mu = s * (1.f / HH);
            pf[F_MU + m] = mu;
            pf[F_RS + m] = rsqrtf(s2 * (1.f / HH) - mu * mu + EPSLN);
        }
    }
    __syncthreads();

    // per-thread A-producer constants: thread covers (m = tid/2, k-half = (tid&1)*16)
    const int am = tid >> 1, ah = (tid & 1) * 16;
    const float AP0 = pf[F_PTS + am * 3 + 0];
    const float AP1 = pf[F_PTS + am * 3 + 1];
    const float AP2 = pf[F_PTS + am * 3 + 2];
    const float AMU = pf[F_MU + am];
    const float ARS = pf[F_RS + am];
    const uint32_t a_prod_base = sbase + (uint32_t)(am * 144 + ah * 4);

    const float* Wsrc = g_W2T + (size_t)ci * K2 * HH;
    const uint32_t b_cp_dst = sbase + (uint32_t)(tid * 144);   // row n = tid
    const float*   b_cp_src = Wsrc + (size_t)tid * HH;

    // warp tile: wm = wid>>2 (rows wm*64..), wn = wid&3 (cols wn*64..)
    const int wm = wid >> 2, wn = wid & 3;
    const int grp = lane >> 3, r8 = lane & 7;
    const uint32_t a_lane = (uint32_t)((r8 + ((grp & 1) << 3)) * 144 + (grp >> 1) * 16)
                          + (uint32_t)(wm * 64 * 144);
    const uint32_t b_lane = (uint32_t)((r8 + ((grp >> 1) << 3)) * 144 + (grp & 1) * 16)
                          + (uint32_t)(wn * 64 * 144);

    float acc[128];
#pragma unroll
    for (int i = 0; i < 128; i++) acc[i] = 0.f;

    // A producer: recompute h1 + LN1 + lrelu, tf32, into Abuf
    auto produce_A = [&](int c, uint32_t abuf) {
        char* dst = (char*)smem_raw + (abuf - sbase) + (a_prod_base - sbase);
        (void)dst;
        const uint32_t base = abuf + (a_prod_base - sbase);
#pragma unroll
        for (int q = 0; q < 4; q++) {
            const int k = c * KC + ah + q * 4;
            const float4 a0 = *(const float4*)(pf + F_W1 + k);
            const float4 a1 = *(const float4*)(pf + F_W1 + 512 + k);
            const float4 a2 = *(const float4*)(pf + F_W1 + 1024 + k);
            const float4 bbv= *(const float4*)(pf + F_B1 + k);
            const float4 gg = *(const float4*)(pf + F_G1 + k);
            const float4 ee = *(const float4*)(pf + F_BE1 + k);
            float y0 = (fmaf(AP0, a0.x, fmaf(AP1, a1.x, fmaf(AP2, a2.x, bbv.x))) - AMU) * ARS;
            float y1 = (fmaf(AP0, a0.y, fmaf(AP1, a1.y, fmaf(AP2, a2.y, bbv.y))) - AMU) * ARS;
            float y2 = (fmaf(AP0, a0.z, fmaf(AP1, a1.z, fmaf(AP2, a2.z, bbv.z))) - AMU) * ARS;
            float y3 = (fmaf(AP0, a0.w, fmaf(AP1, a1.w, fmaf(AP2, a2.w, bbv.w))) - AMU) * ARS;
            y0 = fmaf(y0, gg.x, ee.x); y1 = fmaf(y1, gg.y, ee.y);
            y2 = fmaf(y2, gg.z, ee.z); y3 = fmaf(y3, gg.w, ee.w);
            y0 = y0 >= 0.f ? y0 : SLOPE * y0;
            y1 = y1 >= 0.f ? y1 : SLOPE * y1;
            y2 = y2 >= 0.f ? y2 : SLOPE * y2;
            y3 = y3 >= 0.f ? y3 : SLOPE * y3;
            const uint4 v = make_uint4(f2tf(y0), f2tf(y1), f2tf(y2), f2tf(y3));
            asm volatile("st.shared.v4.b32 [%0], {%1,%2,%3,%4};"
                         :: "r"(base + (uint32_t)(q * 16)),
                            "r"(v.x), "r"(v.y), "r"(v.z), "r"(v.w));
        }
    };
    auto load_B = [&](int c, uint32_t bbuf) {
#pragma unroll
        for (int q = 0; q < 8; q++)
            cp16(b_cp_dst + (bbuf - sbase) + q * 16, b_cp_src + c * KC + q * 4);
        asm volatile("cp.async.commit_group;" ::: "memory");
    };

    // prologue: chunk 0
    produce_A(0, sbase + A0_OFF);
    load_B(0, sbase + B0_OFF);

#pragma unroll 1
    for (int c = 0; c < NCH; c++) {
        asm volatile("cp.async.wait_group 0;" ::: "memory");
        __syncthreads();
        if (c < NCH - 1) {
            load_B(c + 1, sbase + ((c & 1) ? B0_OFF : B1_OFF));
            produce_A(c + 1, sbase + ((c & 1) ? A0_OFF : A1_OFF));
        }
        const uint32_t abuf = sbase + ((c & 1) ? A1_OFF : A0_OFF);
        const uint32_t bbuf = sbase + ((c & 1) ? B1_OFF : B0_OFF);
#pragma unroll
        for (int ks = 0; ks < 4; ks++) {
            const uint32_t koff = (uint32_t)(ks * 32);
            uint32_t af[4][4], bf[4][4];
#pragma unroll
            for (int mt = 0; mt < 4; mt++)
                ldsm4(af[mt], abuf + a_lane + (uint32_t)(mt * 2304) + koff);
#pragma unroll
            for (int p = 0; p < 4; p++)
                ldsm4(bf[p], bbuf + b_lane + (uint32_t)(p * 2304) + koff);
#pragma unroll
            for (int mt = 0; mt < 4; mt++)
#pragma unroll
                for (int p = 0; p < 4; p++) {
                    mma_tf32(&acc[mt * 32 + (2 * p) * 4],     af[mt], bf[p][0], bf[p][1]);
                    mma_tf32(&acc[mt * 32 + (2 * p + 1) * 4], af[mt], bf[p][2], bf[p][3]);
                }
        }
    }
    __syncthreads();   // all mma done before overwriting buffer region with C

    // ---- store acc to smem C [128][CSTR] ----
    {
        const int rbase = wm * 64 + (lane >> 2);
        const int cbase = wn * 64 + 2 * (lane & 3);
#pragma unroll
        for (int mt = 0; mt < 4; mt++)
#pragma unroll
            for (int nt = 0; nt < 8; nt++) {
                const float* a4 = &acc[mt * 32 + nt * 4];
                const int r0 = rbase + mt * 16, cc = cbase + nt * 8;
                *(float2*)(csm + r0 * CSTR + cc)       = make_float2(a4[0], a4[1]);
                *(float2*)(csm + (r0 + 8) * CSTR + cc) = make_float2(a4[2], a4[3]);
            }
    }
    __syncthreads();

    // ---- epilogue: bias2 + LN2 + lrelu + GEMM3 (N=3) ----
#pragma unroll 1
    for (int rr = 0; rr < 16; rr++) {
        const int m = wid * 16 + rr;
        float fv[8];
        float s = 0.f, s2 = 0.f;
#pragma unroll
        for (int j = 0; j < 8; j++) {
            const int n = lane + 32 * j;
            fv[j] = csm[m * CSTR + n] + pf[F_B2 + n];
            s += fv[j];
            s2 = fmaf(fv[j], fv[j], s2);
        }
        s  = warp_sum(s);
        s2 = warp_sum(s2);
        const float mu  = s * (1.f / K2);
        const float inv = rsqrtf(s2 * (1.f / K2) - mu * mu + EPSLN);
        float o0 = 0.f, o1 = 0.f, o2 = 0.f;
#pragma unroll
        for (int j = 0; j < 8; j++) {
            const int n = lane + 32 * j;
            float y = (fv[j] - mu) * inv * pf[F_G2 + n] + pf[F_BE2 + n];
            y = y >= 0.f ? y : SLOPE * y;
            o0 = fmaf(y, pf[F_W3 + n * 3 + 0], o0);
            o1 = fmaf(y, pf[F_W3 + n * 3 + 1], o1);
            o2 = fmaf(y, pf[F_W3 + n * 3 + 2], o2);
        }
        o0 = warp_sum(o0); o1 = warp_sum(o1); o2 = warp_sum(o2);
        if (lane == 0) {
            float* op = out + (size_t)(bIdx * NN + m0 + m) * 3;
            op[0] = o0 + pf[F_B3 + 0];
            op[1] = o1 + pf[F_B3 + 1];
            op[2] = o2 + pf[F_B3 + 2];
        }
    }
}

extern "C" void kernel_launch(void* const* d_in, const int* in_sizes, int n_in,
                              void* d_out, int out_size)
{
    const float* points = (const float*)d_in[0];
    const int*   cat    = (const int*)  d_in[1];
    const float* W1     = (const float*)d_in[2];
    const float* b1     = (const float*)d_in[3];
    const float* g1     = (const float*)d_in[4];
    const float* be1    = (const float*)d_in[5];
    const float* W2     = (const float*)d_in[6];
    const float* b2     = (const float*)d_in[7];
    const float* g2     = (const float*)d_in[8];
    const float* be2    = (const float*)d_in[9];
    const float* W3     = (const float*)d_in[10];
    const float* b3     = (const float*)d_in[11];
    float* out = (float*)d_out;

    cudaFuncSetAttribute(shape_prior_mma,
                         cudaFuncAttributeMaxDynamicSharedMemorySize, SMEM_TOTAL);

    transpose_w2<<<dim3(HH / 32, K2 / 32, NE), dim3(32, 8)>>>(W2);
    shape_prior_mma<<<dim3(NN / TM, BB), THREADS, SMEM_TOTAL>>>(
        points, cat, W1, b1, g1, be1, b2, g2, be2, W3, b3, out);
}

// round 4
// speedup vs baseline: 3.3745x; 1.1061x over previous
#include <cuda_runtime.h>
#include <cstdint>

#define BB      32
#define NN      8192
#define HH      512
#define K2      256
#define TM      128
#define THREADS 512
#define EPSLN   1e-5f
#define SLOPE   0.2f
#define KC      32
#define NCH     (HH / KC)       // 16 k-chunks
#define NE      10

// Transposed + tf32-rounded W2 scratch: W2T[e][n][k] = tf32(W2[e][k][n])
__device__ float g_W2T[NE * K2 * HH];

// ---------------- smem layout (bytes) ----------------
//   A0 @ 0      (128 rows x 144B = 18432)
//   A1 @ 18432
//   B0 @ 36864  (256 rows x 144B = 36864)
//   B1 @ 73728            (ends 110592)
// Epilogue C[128][258] reuses [0, 132096)
// Params (floats) @ 132096
#define A0_OFF 0u
#define A1_OFF 18432u
#define B0_OFF 36864u
#define B1_OFF 73728u
#define CSTR   258
#define P_OFF  132096u
#define F_W1    0             // [3][512]
#define F_B1    1536
#define F_G1    2048
#define F_BE1   2560
#define F_B2    3072
#define F_G2    3328
#define F_BE2   3584
#define F_W3    3840          // [256][3]
#define F_B3    4608
#define F_PTS   4612          // [128][3]
#define F_MU    4996
#define F_RS    5124
#define F_END   5252
#define SMEM_TOTAL (P_OFF + F_END * 4)   // 153104 B

__device__ __forceinline__ uint32_t smem_u32(const void* p) {
    uint32_t a;
    asm("{ .reg .u64 t; cvta.to.shared.u64 t, %1; cvt.u32.u64 %0, t; }" : "=r"(a) : "l"(p));
    return a;
}
__device__ __forceinline__ uint32_t f2tf(float x) {
    uint32_t r; asm("cvt.rna.tf32.f32 %0, %1;" : "=r"(r) : "f"(x)); return r;
}
__device__ __forceinline__ float warp_sum(float v) {
#pragma unroll
    for (int o = 16; o; o >>= 1) v += __shfl_xor_sync(0xffffffffu, v, o);
    return v;
}
__device__ __forceinline__ void ldsm4(uint32_t* r, uint32_t addr) {
    asm volatile("ldmatrix.sync.aligned.m8n8.x4.shared.b16 {%0,%1,%2,%3}, [%4];"
                 : "=r"(r[0]), "=r"(r[1]), "=r"(r[2]), "=r"(r[3]) : "r"(addr));
}
__device__ __forceinline__ void mma_tf32(float* c, const uint32_t* a, uint32_t b0, uint32_t b1) {
    asm volatile("mma.sync.aligned.m16n8k8.row.col.f32.tf32.tf32.f32 "
                 "{%0,%1,%2,%3}, {%4,%5,%6,%7}, {%8,%9}, {%0,%1,%2,%3};"
                 : "+f"(c[0]), "+f"(c[1]), "+f"(c[2]), "+f"(c[3])
                 : "r"(a[0]), "r"(a[1]), "r"(a[2]), "r"(a[3]), "r"(b0), "r"(b1));
}
__device__ __forceinline__ void cp16(uint32_t dst, const void* src) {
    asm volatile("cp.async.cg.shared.global [%0], [%1], 16;" :: "r"(dst), "l"(src));
}

// ------------- W2 transpose + tf32 round pre-kernel -------------
__global__ void transpose_w2(const float* __restrict__ W2) {
    __shared__ float t[32][33];
    const int e  = blockIdx.z;
    const int kb = blockIdx.x * 32, nb = blockIdx.y * 32;
    const int tx = threadIdx.x, ty = threadIdx.y;
    const float* src = W2 + e * HH * K2;
    float* dst = g_W2T + e * K2 * HH;
#pragma unroll
    for (int r = 0; r < 32; r += 8)
        t[ty + r][tx] = src[(kb + ty + r) * K2 + nb + tx];
    __syncthreads();
#pragma unroll
    for (int r = 0; r < 32; r += 8)
        dst[(nb + ty + r) * HH + kb + tx] = __uint_as_float(f2tf(t[tx][ty + r]));
}

extern __shared__ char smem_raw[];

__global__ __launch_bounds__(THREADS, 1)
void shape_prior_mma(const float* __restrict__ points, const int* __restrict__ cat,
                     const float* __restrict__ W1, const float* __restrict__ b1,
                     const float* __restrict__ g1, const float* __restrict__ be1,
                     const float* __restrict__ b2, const float* __restrict__ g2,
                     const float* __restrict__ be2,
                     const float* __restrict__ W3, const float* __restrict__ b3,
                     float* __restrict__ out)
{
    float* pf  = (float*)(smem_raw + P_OFF);
    float* csm = (float*)smem_raw;
    const int tid  = threadIdx.x;
    const int wid  = tid >> 5;
    const int lane = tid & 31;
    const int bIdx = blockIdx.y;
    const int m0   = blockIdx.x * TM;
    const int ci   = cat[bIdx];
    const uint32_t sbase = smem_u32(smem_raw);

    // ---- stage per-expert params + points ----
    for (int i = tid; i < 3 * HH; i += THREADS) pf[F_W1 + i] = W1[ci * 3 * HH + i];
    for (int i = tid; i < HH; i += THREADS) {
        pf[F_B1  + i] = b1 [ci * HH + i];
        pf[F_G1  + i] = g1 [ci * HH + i];
        pf[F_BE1 + i] = be1[ci * HH + i];
    }
    for (int i = tid; i < K2; i += THREADS) {
        pf[F_B2  + i] = b2 [ci * K2 + i];
        pf[F_G2  + i] = g2 [ci * K2 + i];
        pf[F_BE2 + i] = be2[ci * K2 + i];
    }
    for (int i = tid; i < K2 * 3; i += THREADS) pf[F_W3 + i] = W3[ci * K2 * 3 + i];
    if (tid < 3) pf[F_B3 + tid] = b3[ci * 3 + tid];
    for (int i = tid; i < TM * 3; i += THREADS)
        pf[F_PTS + i] = points[(size_t)(bIdx * NN + m0) * 3 + i];
    __syncthreads();

    // ---- pass 1: per-point LN1 stats (mu, rstd); 16 warps x 8 points ----
#pragma unroll 1
    for (int p = 0; p < 8; p++) {
        const int m = wid * 8 + p;
        const float p0 = pf[F_PTS + m * 3 + 0];
        const float p1 = pf[F_PTS + m * 3 + 1];
        const float p2 = pf[F_PTS + m * 3 + 2];
        float s = 0.f, s2 = 0.f;
#pragma unroll
        for (int q = 0; q < 4; q++) {
            const int k = lane * 16 + q * 4;
            const float4 a0 = *(const float4*)(pf + F_W1 + k);
            const float4 a1 = *(const float4*)(pf + F_W1 + 512 + k);
            const float4 a2 = *(const float4*)(pf + F_W1 + 1024 + k);
            const float4 bb = *(const float4*)(pf + F_B1 + k);
            const float h0 = fmaf(p0, a0.x, fmaf(p1, a1.x, fmaf(p2, a2.x, bb.x)));
            const float h1v= fmaf(p0, a0.y, fmaf(p1, a1.y, fmaf(p2, a2.y, bb.y)));
            const float h2 = fmaf(p0, a0.z, fmaf(p1, a1.z, fmaf(p2, a2.z, bb.z)));
            const float h3 = fmaf(p0, a0.w, fmaf(p1, a1.w, fmaf(p2, a2.w, bb.w)));
            s += h0 + h1v + h2 + h3;
            s2 = fmaf(h0, h0, s2); s2 = fmaf(h1v, h1v, s2);
            s2 = fmaf(h2, h2, s2); s2 = fmaf(h3, h3, s2);
        }
        s  = warp_sum(s);
        s2 = warp_sum(s2);
        if (lane == 0) {
            const float mu = s * (1.f / HH);
            pf[F_MU + m] = mu;
            pf[F_RS + m] = rsqrtf(s2 * (1.f / HH) - mu * mu + EPSLN);
        }
    }
    __syncthreads();

    // A producer: thread covers (m = tid/4, k-quarter = (tid&3)*8 floats)
    const int am = tid >> 2, aq = (tid & 3) * 8;
    const float AP0 = pf[F_PTS + am * 3 + 0];
    const float AP1 = pf[F_PTS + am * 3 + 1];
    const float AP2 = pf[F_PTS + am * 3 + 2];
    const float AMU = pf[F_MU + am];
    const float ARS = pf[F_RS + am];
    const uint32_t a_prod_off = (uint32_t)(am * 144 + aq * 4);

    const float* Wsrc = g_W2T + (size_t)ci * K2 * HH;
    // B producer: row = tid/2 (0..255), half = tid&1 (16 floats = 4 cp16)
    const int bn = tid >> 1, bh = tid & 1;
    const uint32_t b_cp_off = (uint32_t)(bn * 144 + bh * 64);
    const float*   b_cp_src = Wsrc + (size_t)bn * HH + bh * 16;

    // warp tile: wm = wid>>2 (rows wm*32..), wn = wid&3 (cols wn*64..)
    const int wm = wid >> 2, wn = wid & 3;
    const int grp = lane >> 3, r8 = lane & 7;
    const uint32_t a_lane = (uint32_t)((r8 + ((grp & 1) << 3)) * 144 + (grp >> 1) * 16)
                          + (uint32_t)(wm * 32 * 144);
    const uint32_t b_lane = (uint32_t)((r8 + ((grp >> 1) << 3)) * 144 + (grp & 1) * 16)
                          + (uint32_t)(wn * 64 * 144);

    float acc[64];
#pragma unroll
    for (int i = 0; i < 64; i++) acc[i] = 0.f;

    auto produce_A = [&](int c, uint32_t abuf_off) {
        const uint32_t base = sbase + abuf_off + a_prod_off;
#pragma unroll
        for (int q = 0; q < 2; q++) {
            const int k = c * KC + aq + q * 4;
            const float4 a0 = *(const float4*)(pf + F_W1 + k);
            const float4 a1 = *(const float4*)(pf + F_W1 + 512 + k);
            const float4 a2 = *(const float4*)(pf + F_W1 + 1024 + k);
            const float4 bbv= *(const float4*)(pf + F_B1 + k);
            const float4 gg = *(const float4*)(pf + F_G1 + k);
            const float4 ee = *(const float4*)(pf + F_BE1 + k);
            float y0 = (fmaf(AP0, a0.x, fmaf(AP1, a1.x, fmaf(AP2, a2.x, bbv.x))) - AMU) * ARS;
            float y1 = (fmaf(AP0, a0.y, fmaf(AP1, a1.y, fmaf(AP2, a2.y, bbv.y))) - AMU) * ARS;
            float y2 = (fmaf(AP0, a0.z, fmaf(AP1, a1.z, fmaf(AP2, a2.z, bbv.z))) - AMU) * ARS;
            float y3 = (fmaf(AP0, a0.w, fmaf(AP1, a1.w, fmaf(AP2, a2.w, bbv.w))) - AMU) * ARS;
            y0 = fmaf(y0, gg.x, ee.x); y1 = fmaf(y1, gg.y, ee.y);
            y2 = fmaf(y2, gg.z, ee.z); y3 = fmaf(y3, gg.w, ee.w);
            y0 = y0 >= 0.f ? y0 : SLOPE * y0;
            y1 = y1 >= 0.f ? y1 : SLOPE * y1;
            y2 = y2 >= 0.f ? y2 : SLOPE * y2;
            y3 = y3 >= 0.f ? y3 : SLOPE * y3;
            const uint4 v = make_uint4(f2tf(y0), f2tf(y1), f2tf(y2), f2tf(y3));
            asm volatile("st.shared.v4.b32 [%0], {%1,%2,%3,%4};"
                         :: "r"(base + (uint32_t)(q * 16)),
                            "r"(v.x), "r"(v.y), "r"(v.z), "r"(v.w));
        }
    };
    auto load_B = [&](int c, uint32_t bbuf_off) {
#pragma unroll
        for (int q = 0; q < 4; q++)
            cp16(sbase + bbuf_off + b_cp_off + q * 16, b_cp_src + c * KC + q * 4);
        asm volatile("cp.async.commit_group;" ::: "memory");
    };

    produce_A(0, A0_OFF);
    load_B(0, B0_OFF);

#pragma unroll 1
    for (int c = 0; c < NCH; c++) {
        asm volatile("cp.async.wait_group 0;" ::: "memory");
        __syncthreads();
        if (c < NCH - 1) {
            load_B(c + 1, (c & 1) ? B0_OFF : B1_OFF);
            produce_A(c + 1, (c & 1) ? A0_OFF : A1_OFF);
        }
        const uint32_t abuf = sbase + ((c & 1) ? A1_OFF : A0_OFF);
        const uint32_t bbuf = sbase + ((c & 1) ? B1_OFF : B0_OFF);
#pragma unroll
        for (int ks = 0; ks < 4; ks++) {
            const uint32_t koff = (uint32_t)(ks * 32);
            uint32_t af[2][4], bf[4][4];
#pragma unroll
            for (int mt = 0; mt < 2; mt++)
                ldsm4(af[mt], abuf + a_lane + (uint32_t)(mt * 2304) + koff);
#pragma unroll
            for (int p = 0; p < 4; p++)
                ldsm4(bf[p], bbuf + b_lane + (uint32_t)(p * 2304) + koff);
#pragma unroll
            for (int mt = 0; mt < 2; mt++)
#pragma unroll
                for (int p = 0; p < 4; p++) {
                    mma_tf32(&acc[mt * 32 + (2 * p) * 4],     af[mt], bf[p][0], bf[p][1]);
                    mma_tf32(&acc[mt * 32 + (2 * p + 1) * 4], af[mt], bf[p][2], bf[p][3]);
                }
        }
    }
    __syncthreads();   // all mma done before overwriting buffers with C

    // ---- store acc to smem C [128][CSTR] ----
    {
        const int rbase = wm * 32 + (lane >> 2);
        const int cbase = wn * 64 + 2 * (lane & 3);
#pragma unroll
        for (int mt = 0; mt < 2; mt++)
#pragma unroll
            for (int nt = 0; nt < 8; nt++) {
                const float* a4 = &acc[mt * 32 + nt * 4];
                const int r0 = rbase + mt * 16, cc = cbase + nt * 8;
                *(float2*)(csm + r0 * CSTR + cc)       = make_float2(a4[0], a4[1]);
                *(float2*)(csm + (r0 + 8) * CSTR + cc) = make_float2(a4[2], a4[3]);
            }
    }
    __syncthreads();

    // ---- epilogue: bias2 + LN2 + lrelu + GEMM3 (N=3); 16 warps x 8 rows ----
#pragma unroll 1
    for (int rr = 0; rr < 8; rr++) {
        const int m = wid * 8 + rr;
        float fv[8];
        float s = 0.f, s2 = 0.f;
#pragma unroll
        for (int j = 0; j < 8; j++) {
            const int n = lane + 32 * j;
            fv[j] = csm[m * CSTR + n] + pf[F_B2 + n];
            s += fv[j];
            s2 = fmaf(fv[j], fv[j], s2);
        }
        s  = warp_sum(s);
        s2 = warp_sum(s2);
        const float mu  = s * (1.f / K2);
        const float inv = rsqrtf(s2 * (1.f / K2) - mu * mu + EPSLN);
        float o0 = 0.f, o1 = 0.f, o2 = 0.f;
#pragma unroll
        for (int j = 0; j < 8; j++) {
            const int n = lane + 32 * j;
            float y = (fv[j] - mu) * inv * pf[F_G2 + n] + pf[F_BE2 + n];
            y = y >= 0.f ? y : SLOPE * y;
            o0 = fmaf(y, pf[F_W3 + n * 3 + 0], o0);
            o1 = fmaf(y, pf[F_W3 + n * 3 + 1], o1);
            o2 = fmaf(y, pf[F_W3 + n * 3 + 2], o2);
        }
        o0 = warp_sum(o0); o1 = warp_sum(o1); o2 = warp_sum(o2);
        if (lane == 0) {
            float* op = out + (size_t)(bIdx * NN + m0 + m) * 3;
            op[0] = o0 + pf[F_B3 + 0];
            op[1] = o1 + pf[F_B3 + 1];
            op[2] = o2 + pf[F_B3 + 2];
        }
    }
}

extern "C" void kernel_launch(void* const* d_in, const int* in_sizes, int n_in,
                              void* d_out, int out_size)
{
    const float* points = (const float*)d_in[0];
    const int*   cat    = (const int*)  d_in[1];
    const float* W1     = (const float*)d_in[2];
    const float* b1     = (const float*)d_in[3];
    const float* g1     = (const float*)d_in[4];
    const float* be1    = (const float*)d_in[5];
    const float* W2     = (const float*)d_in[6];
    const float* b2     = (const float*)d_in[7];
    const float* g2     = (const float*)d_in[8];
    const float* be2    = (const float*)d_in[9];
    const float* W3     = (const float*)d_in[10];
    const float* b3     = (const float*)d_in[11];
    float* out = (float*)d_out;

    cudaFuncSetAttribute(shape_prior_mma,
                         cudaFuncAttributeMaxDynamicSharedMemorySize, SMEM_TOTAL);

    transpose_w2<<<dim3(HH / 32, K2 / 32, NE), dim3(32, 8)>>>(W2);
    shape_prior_mma<<<dim3(NN / TM, BB), THREADS, SMEM_TOTAL>>>(
        points, cat, W1, b1, g1, be1, b2, g2, be2, W3, b3, out);
}

// round 5
// speedup vs baseline: 3.8714x; 1.1473x over previous
#include <cuda_runtime.h>
#include <cstdint>

#define BB      32
#define NN      8192
#define HH      512
#define K2      256
#define TM      128
#define THREADS 512
#define EPSLN   1e-5f
#define SLOPE   0.2f
#define KC      32
#define NCH     (HH / KC)       // 16 k-chunks
#define NE      10

// Row stride in the B chunk image: 32 tf32 + 4 pad floats = 144 B
#define BROW    36
#define BCHUNK  (K2 * BROW * 4)        // 36864 bytes per chunk
#define ECHUNK  (NCH * K2 * BROW)      // floats per expert

// Packed, padded, tf32-rounded W2: g_W2C[e][chunk][n (256)][kk (36)]
__device__ float g_W2C[NE * ECHUNK];

// ---------------- smem layout (bytes) ----------------
//   A0 @ 0       (128 rows x 144B = 18432)
//   A1 @ 18432
//   B ring: 4 x 36864 @ 36864                (ends 184320)
// Epilogue C[128][258] (132096 B) reuses [0, 132096)
// Params (floats) @ 184320, mbarriers after
#define A0_OFF 0u
#define A1_OFF 18432u
#define B0_OFF 36864u
#define CSTR   258
#define P_OFF  184320u
#define F_W1    0             // [3][512]
#define F_B1    1536
#define F_G1    2048
#define F_BE1   2560
#define F_B2    3072
#define F_G2    3328
#define F_BE2   3584
#define F_W3    3840          // [256][3]
#define F_B3    4608
#define F_PTS   4612          // [128][3]
#define F_MU    4996
#define F_RS    5124
#define F_END   5252
#define MB_OFF  (P_OFF + F_END * 4)    // 205328, 8B aligned; 4 x 8B mbarriers
#define SMEM_TOTAL (MB_OFF + 32)       // 205360 B

__device__ __forceinline__ uint32_t smem_u32(const void* p) {
    uint32_t a;
    asm("{ .reg .u64 t; cvta.to.shared.u64 t, %1; cvt.u32.u64 %0, t; }" : "=r"(a) : "l"(p));
    return a;
}
__device__ __forceinline__ uint32_t f2tf(float x) {
    uint32_t r; asm("cvt.rna.tf32.f32 %0, %1;" : "=r"(r) : "f"(x)); return r;
}
__device__ __forceinline__ float warp_sum(float v) {
#pragma unroll
    for (int o = 16; o; o >>= 1) v += __shfl_xor_sync(0xffffffffu, v, o);
    return v;
}
__device__ __forceinline__ void ldsm4(uint32_t* r, uint32_t addr) {
    asm volatile("ldmatrix.sync.aligned.m8n8.x4.shared.b16 {%0,%1,%2,%3}, [%4];"
                 : "=r"(r[0]), "=r"(r[1]), "=r"(r[2]), "=r"(r[3]) : "r"(addr));
}
__device__ __forceinline__ void mma_tf32(float* c, const uint32_t* a, uint32_t b0, uint32_t b1) {
    asm volatile("mma.sync.aligned.m16n8k8.row.col.f32.tf32.tf32.f32 "
                 "{%0,%1,%2,%3}, {%4,%5,%6,%7}, {%8,%9}, {%0,%1,%2,%3};"
                 : "+f"(c[0]), "+f"(c[1]), "+f"(c[2]), "+f"(c[3])
                 : "r"(a[0]), "r"(a[1]), "r"(a[2]), "r"(a[3]), "r"(b0), "r"(b1));
}
__device__ __forceinline__ void mbar_wait(uint32_t addr, uint32_t parity) {
    asm volatile(
        "{\n\t.reg .pred P;\n\t"
        "WL_%=:\n\t"
        "mbarrier.try_wait.parity.acquire.cta.shared::cta.b64 P, [%0], %1, 0x989680;\n\t"
        "@P bra.uni WD_%=;\n\t"
        "bra.uni WL_%=;\n\t"
        "WD_%=:\n\t}"
        :: "r"(addr), "r"(parity) : "memory");
}
__device__ __forceinline__ void bulk_in(uint32_t dst, const void* src, uint32_t bytes,
                                        uint32_t mbar) {
    asm volatile(
        "cp.async.bulk.shared::cluster.global.mbarrier::complete_tx::bytes "
        "[%0], [%1], %2, [%3];"
        :: "r"(dst), "l"(src), "r"(bytes), "r"(mbar) : "memory");
}
__device__ __forceinline__ void expect_tx(uint32_t mbar, uint32_t bytes) {
    asm volatile("mbarrier.arrive.expect_tx.shared.b64 _, [%0], %1;"
                 :: "r"(mbar), "r"(bytes) : "memory");
}

// ------------- W2 pack pre-kernel: transpose + tf32 + smem-image layout -------------
__global__ void pack_w2(const float* __restrict__ W2) {
    __shared__ float t[32][33];
    const int e  = blockIdx.z;
    const int kb = blockIdx.x * 32, nb = blockIdx.y * 32;
    const int tx = threadIdx.x, ty = threadIdx.y;
    const float* src = W2 + e * HH * K2;
    // t[k-local][n-local]
#pragma unroll
    for (int r = 0; r < 32; r += 8)
        t[ty + r][tx] = src[(kb + ty + r) * K2 + nb + tx];
    __syncthreads();
    // chunk = kb/32, kk = tx, n = nb+ty+r
    float* dst = g_W2C + ((size_t)(e * NCH + (kb >> 5)) * K2) * BROW;
#pragma unroll
    for (int r = 0; r < 32; r += 8)
        dst[(nb + ty + r) * BROW + tx] = __uint_as_float(f2tf(t[tx][ty + r]));
}

extern __shared__ char smem_raw[];

__global__ __launch_bounds__(THREADS, 1)
void shape_prior_mma(const float* __restrict__ points, const int* __restrict__ cat,
                     const float* __restrict__ W1, const float* __restrict__ b1,
                     const float* __restrict__ g1, const float* __restrict__ be1,
                     const float* __restrict__ b2, const float* __restrict__ g2,
                     const float* __restrict__ be2,
                     const float* __restrict__ W3, const float* __restrict__ b3,
                     float* __restrict__ out)
{
    float* pf  = (float*)(smem_raw + P_OFF);
    float* csm = (float*)smem_raw;
    const int tid  = threadIdx.x;
    const int wid  = tid >> 5;
    const int lane = tid & 31;
    const int bIdx = blockIdx.y;
    const int m0   = blockIdx.x * TM;
    const int ci   = cat[bIdx];
    const uint32_t sbase = smem_u32(smem_raw);

    // ---- stage per-expert params + points ----
    for (int i = tid; i < 3 * HH; i += THREADS) pf[F_W1 + i] = W1[ci * 3 * HH + i];
    for (int i = tid; i < HH; i += THREADS) {
        pf[F_B1  + i] = b1 [ci * HH + i];
        pf[F_G1  + i] = g1 [ci * HH + i];
        pf[F_BE1 + i] = be1[ci * HH + i];
    }
    for (int i = tid; i < K2; i += THREADS) {
        pf[F_B2  + i] = b2 [ci * K2 + i];
        pf[F_G2  + i] = g2 [ci * K2 + i];
        pf[F_BE2 + i] = be2[ci * K2 + i];
    }
    for (int i = tid; i < K2 * 3; i += THREADS) pf[F_W3 + i] = W3[ci * K2 * 3 + i];
    if (tid < 3) pf[F_B3 + tid] = b3[ci * 3 + tid];
    for (int i = tid; i < TM * 3; i += THREADS)
        pf[F_PTS + i] = points[(size_t)(bIdx * NN + m0) * 3 + i];
    if (tid == 0) {
#pragma unroll
        for (int j = 0; j < 4; j++)
            asm volatile("mbarrier.init.shared.b64 [%0], 1;"
                         :: "r"(sbase + MB_OFF + 8u * j) : "memory");
    }
    __syncthreads();

    const float* Wsrc = g_W2C + (size_t)ci * ECHUNK;
    // kick off B chunks 0..2 (prefetch distance 3)
    if (tid == 0) {
#pragma unroll
        for (int j = 0; j < 3; j++) {
            const uint32_t mb = sbase + MB_OFF + 8u * j;
            expect_tx(mb, BCHUNK);
            bulk_in(sbase + B0_OFF + (uint32_t)BCHUNK * j,
                    Wsrc + (size_t)j * K2 * BROW, BCHUNK, mb);
        }
    }

    // ---- pass 1: per-point LN1 stats (mu, rstd); 16 warps x 8 points ----
#pragma unroll 1
    for (int p = 0; p < 8; p++) {
        const int m = wid * 8 + p;
        const float p0 = pf[F_PTS + m * 3 + 0];
        const float p1 = pf[F_PTS + m * 3 + 1];
        const float p2 = pf[F_PTS + m * 3 + 2];
        float s = 0.f, s2 = 0.f;
#pragma unroll
        for (int q = 0; q < 4; q++) {
            const int k = lane * 16 + q * 4;
            const float4 a0 = *(const float4*)(pf + F_W1 + k);
            const float4 a1 = *(const float4*)(pf + F_W1 + 512 + k);
            const float4 a2 = *(const float4*)(pf + F_W1 + 1024 + k);
            const float4 bb = *(const float4*)(pf + F_B1 + k);
            const float h0 = fmaf(p0, a0.x, fmaf(p1, a1.x, fmaf(p2, a2.x, bb.x)));
            const float h1v= fmaf(p0, a0.y, fmaf(p1, a1.y, fmaf(p2, a2.y, bb.y)));
            const float h2 = fmaf(p0, a0.z, fmaf(p1, a1.z, fmaf(p2, a2.z, bb.z)));
            const float h3 = fmaf(p0, a0.w, fmaf(p1, a1.w, fmaf(p2, a2.w, bb.w)));
            s += h0 + h1v + h2 + h3;
            s2 = fmaf(h0, h0, s2); s2 = fmaf(h1v, h1v, s2);
            s2 = fmaf(h2, h2, s2); s2 = fmaf(h3, h3, s2);
        }
        s  = warp_sum(s);
        s2 = warp_sum(s2);
        if (lane == 0) {
            const float mu = s * (1.f / HH);
            pf[F_MU + m] = mu;
            pf[F_RS + m] = rsqrtf(s2 * (1.f / HH) - mu * mu + EPSLN);
        }
    }
    __syncthreads();

    // A producer: thread covers (m = tid/4, k-quarter = (tid&3)*8 floats)
    const int am = tid >> 2, aq = (tid & 3) * 8;
    const float AP0 = pf[F_PTS + am * 3 + 0];
    const float AP1 = pf[F_PTS + am * 3 + 1];
    const float AP2 = pf[F_PTS + am * 3 + 2];
    const float AMU = pf[F_MU + am];
    const float ARS = pf[F_RS + am];
    const uint32_t a_prod_off = (uint32_t)(am * 144 + aq * 4);

    // warp tile: wm = wid>>2 (rows wm*32..), wn = wid&3 (cols wn*64..)
    const int wm = wid >> 2, wn = wid & 3;
    const int grp = lane >> 3, r8 = lane & 7;
    const uint32_t a_lane = (uint32_t)((r8 + ((grp & 1) << 3)) * 144 + (grp >> 1) * 16)
                          + (uint32_t)(wm * 32 * 144);
    const uint32_t b_lane = (uint32_t)((r8 + ((grp >> 1) << 3)) * 144 + (grp & 1) * 16)
                          + (uint32_t)(wn * 64 * 144);

    float acc[64];
#pragma unroll
    for (int i = 0; i < 64; i++) acc[i] = 0.f;

    auto produce_A = [&](int c, uint32_t abuf_off) {
        const uint32_t base = sbase + abuf_off + a_prod_off;
#pragma unroll
        for (int q = 0; q < 2; q++) {
            const int k = c * KC + aq + q * 4;
            const float4 a0 = *(const float4*)(pf + F_W1 + k);
            const float4 a1 = *(const float4*)(pf + F_W1 + 512 + k);
            const float4 a2 = *(const float4*)(pf + F_W1 + 1024 + k);
            const float4 bbv= *(const float4*)(pf + F_B1 + k);
            const float4 gg = *(const float4*)(pf + F_G1 + k);
            const float4 ee = *(const float4*)(pf + F_BE1 + k);
            float y0 = (fmaf(AP0, a0.x, fmaf(AP1, a1.x, fmaf(AP2, a2.x, bbv.x))) - AMU) * ARS;
            float y1 = (fmaf(AP0, a0.y, fmaf(AP1, a1.y, fmaf(AP2, a2.y, bbv.y))) - AMU) * ARS;
            float y2 = (fmaf(AP0, a0.z, fmaf(AP1, a1.z, fmaf(AP2, a2.z, bbv.z))) - AMU) * ARS;
            float y3 = (fmaf(AP0, a0.w, fmaf(AP1, a1.w, fmaf(AP2, a2.w, bbv.w))) - AMU) * ARS;
            y0 = fmaf(y0, gg.x, ee.x); y1 = fmaf(y1, gg.y, ee.y);
            y2 = fmaf(y2, gg.z, ee.z); y3 = fmaf(y3, gg.w, ee.w);
            y0 = y0 >= 0.f ? y0 : SLOPE * y0;
            y1 = y1 >= 0.f ? y1 : SLOPE * y1;
            y2 = y2 >= 0.f ? y2 : SLOPE * y2;
            y3 = y3 >= 0.f ? y3 : SLOPE * y3;
            const uint4 v = make_uint4(f2tf(y0), f2tf(y1), f2tf(y2), f2tf(y3));
            asm volatile("st.shared.v4.b32 [%0], {%1,%2,%3,%4};"
                         :: "r"(base + (uint32_t)(q * 16)),
                            "r"(v.x), "r"(v.y), "r"(v.z), "r"(v.w));
        }
    };

    produce_A(0, A0_OFF);

#pragma unroll 1
    for (int c = 0; c < NCH; c++) {
        __syncthreads();   // A(c) visible; all mma(c-1) done -> buf (c+3)&3 free
        if (tid == 0 && c + 3 < NCH) {
            const uint32_t mb = sbase + MB_OFF + 8u * ((c + 3) & 3);
            expect_tx(mb, BCHUNK);
            bulk_in(sbase + B0_OFF + (uint32_t)BCHUNK * ((c + 3) & 3),
                    Wsrc + (size_t)(c + 3) * K2 * BROW, BCHUNK, mb);
        }
        mbar_wait(sbase + MB_OFF + 8u * (c & 3), (c >> 2) & 1);
        if (c < NCH - 1) produce_A(c + 1, (c & 1) ? A0_OFF : A1_OFF);

        const uint32_t abuf = sbase + ((c & 1) ? A1_OFF : A0_OFF);
        const uint32_t bbuf = sbase + B0_OFF + (uint32_t)BCHUNK * (c & 3);
#pragma unroll
        for (int ks = 0; ks < 4; ks++) {
            const uint32_t koff = (uint32_t)(ks * 32);
            uint32_t af[2][4], bf[4][4];
#pragma unroll
            for (int mt = 0; mt < 2; mt++)
                ldsm4(af[mt], abuf + a_lane + (uint32_t)(mt * 2304) + koff);
#pragma unroll
            for (int p = 0; p < 4; p++)
                ldsm4(bf[p], bbuf + b_lane + (uint32_t)(p * 2304) + koff);
#pragma unroll
            for (int mt = 0; mt < 2; mt++)
#pragma unroll
                for (int p = 0; p < 4; p++) {
                    mma_tf32(&acc[mt * 32 + (2 * p) * 4],     af[mt], bf[p][0], bf[p][1]);
                    mma_tf32(&acc[mt * 32 + (2 * p + 1) * 4], af[mt], bf[p][2], bf[p][3]);
                }
        }
    }
    __syncthreads();   // all mma done before overwriting buffers with C

    // ---- store acc to smem C [128][CSTR] ----
    {
        const int rbase = wm * 32 + (lane >> 2);
        const int cbase = wn * 64 + 2 * (lane & 3);
#pragma unroll
        for (int mt = 0; mt < 2; mt++)
#pragma unroll
            for (int nt = 0; nt < 8; nt++) {
                const float* a4 = &acc[mt * 32 + nt * 4];
                const int r0 = rbase + mt * 16, cc = cbase + nt * 8;
                *(float2*)(csm + r0 * CSTR + cc)       = make_float2(a4[0], a4[1]);
                *(float2*)(csm + (r0 + 8) * CSTR + cc) = make_float2(a4[2], a4[3]);
            }
    }
    __syncthreads();

    // ---- epilogue: bias2 + LN2 + lrelu + GEMM3 (N=3); 16 warps x 8 rows ----
#pragma unroll 1
    for (int rr = 0; rr < 8; rr++) {
        const int m = wid * 8 + rr;
        float fv[8];
        float s = 0.f, s2 = 0.f;
#pragma unroll
        for (int j = 0; j < 8; j++) {
            const int n = lane + 32 * j;
            fv[j] = csm[m * CSTR + n] + pf[F_B2 + n];
            s += fv[j];
            s2 = fmaf(fv[j], fv[j], s2);
        }
        s  = warp_sum(s);
        s2 = warp_sum(s2);
        const float mu  = s * (1.f / K2);
        const float inv = rsqrtf(s2 * (1.f / K2) - mu * mu + EPSLN);
        float o0 = 0.f, o1 = 0.f, o2 = 0.f;
#pragma unroll
        for (int j = 0; j < 8; j++) {
            const int n = lane + 32 * j;
            float y = (fv[j] - mu) * inv * pf[F_G2 + n] + pf[F_BE2 + n];
            y = y >= 0.f ? y : SLOPE * y;
            o0 = fmaf(y, pf[F_W3 + n * 3 + 0], o0);
            o1 = fmaf(y, pf[F_W3 + n * 3 + 1], o1);
            o2 = fmaf(y, pf[F_W3 + n * 3 + 2], o2);
        }
        o0 = warp_sum(o0); o1 = warp_sum(o1); o2 = warp_sum(o2);
        if (lane == 0) {
            float* op = out + (size_t)(bIdx * NN + m0 + m) * 3;
            op[0] = o0 + pf[F_B3 + 0];
            op[1] = o1 + pf[F_B3 + 1];
            op[2] = o2 + pf[F_B3 + 2];
        }
    }
}

extern "C" void kernel_launch(void* const* d_in, const int* in_sizes, int n_in,
                              void* d_out, int out_size)
{
    const float* points = (const float*)d_in[0];
    const int*   cat    = (const int*)  d_in[1];
    const float* W1     = (const float*)d_in[2];
    const float* b1     = (const float*)d_in[3];
    const float* g1     = (const float*)d_in[4];
    const float* be1    = (const float*)d_in[5];
    const float* W2     = (const float*)d_in[6];
    const float* b2     = (const float*)d_in[7];
    const float* g2     = (const float*)d_in[8];
    const float* be2    = (const float*)d_in[9];
    const float* W3     = (const float*)d_in[10];
    const float* b3     = (const float*)d_in[11];
    float* out = (float*)d_out;

    cudaFuncSetAttribute(shape_prior_mma,
                         cudaFuncAttributeMaxDynamicSharedMemorySize, SMEM_TOTAL);

    pack_w2<<<dim3(HH / 32, K2 / 32, NE), dim3(32, 8)>>>(W2);
    shape_prior_mma<<<dim3(NN / TM, BB), THREADS, SMEM_TOTAL>>>(
        points, cat, W1, b1, g1, be1, b2, g2, be2, W3, b3, out);
}